// round 14
// baseline (speedup 1.0000x reference)
#include <cuda_runtime.h>
#include <math.h>

// Problem constants
#define NIMG 8
#define CCH  3
#define HI   512
#define WI   512
#define HO   2048
#define WO   2048

__device__ __forceinline__ float sigm(float z) {
    return 1.0f / (1.0f + expf(-z));
}

// Single fused kernel, back-to-front compositing with early termination.
// LANE-INTERLEAVED pixel assignment: thread (lane) handles
//   px(j) = blockIdx.x*128 + lane + j*32,  j = 0..3
// so every gather/store instruction's warp footprint is 32 CONTIGUOUS output
// px -> ~1 L1 wavefront per src gather (vs 2-3 for contiguous-4px threads),
// while per-layer setup still amortizes over 4 px.
// Canvas traffic uses streaming (.cs) scalar accesses (lane-contiguous,
// 128B/instruction: same total wavefronts as float4 form).
__global__ __launch_bounds__(128) void composite_kernel(
    const float* __restrict__ src,   // [8,3,512,512]
    const float* __restrict__ bg,    // [1,3,2048,2048]
    const float* __restrict__ coor,  // [8,4]
    float* __restrict__ out)         // [1,3,2048,2048]
{
    // Folded affine params: ix = ax*px + bx, iy = ay*py + by
    __shared__ float4 sprm[NIMG];

    const int ltid = threadIdx.y * 32 + threadIdx.x;
    if (ltid < NIMG) {
        const int n = ltid;
        float x = sigm(coor[4 * n + 0]) * (float)WO;
        float y = sigm(coor[4 * n + 1]) * (float)HO;
        float w = sigm(coor[4 * n + 2]) * (float)WO;
        float h = sigm(coor[4 * n + 3]) * (float)HO;
        float a  = (float)WO / (w + 1e-8f);
        float tx = (2.0f / (float)WO) * ((float)WO * 0.5f - x) * a;
        float b  = (float)HO / (h + 1e-8f);
        float ty = (2.0f / (float)HO) * ((float)HO * 0.5f - y) * b;
        float ax = a * ((float)WI / (float)WO);
        float bx = ((a * (1.0f / (float)WO - 1.0f) + tx + 1.0f) * (float)WI - 1.0f) * 0.5f;
        float ay = b * ((float)HI / (float)HO);
        float by = ((b * (1.0f / (float)HO - 1.0f) + ty + 1.0f) * (float)HI - 1.0f) * 0.5f;
        sprm[n] = make_float4(ax, bx, ay, by);
    }
    __syncthreads();

    const int px0 = blockIdx.x * 128 + threadIdx.x;      // j-stride = 32
    const int py  = blockIdx.y * 4 + threadIdx.y;
    const int HW  = HO * WO;
    const int base = py * WO + px0;                      // pixel j at base + j*32

    float A[3][4] = {{0.f,0.f,0.f,0.f},{0.f,0.f,0.f,0.f},{0.f,0.f,0.f,0.f}};
    float T[4] = {1.f, 1.f, 1.f, 1.f};

    const float fpy  = (float)py;
    const float fpx0 = (float)px0;

#pragma unroll
    for (int n = NIMG - 1; n >= 0; n--) {
        const float4 p = sprm[n];   // ax, bx, ay, by

        const float iy = fmaf(p.z, fpy, p.w);
        if (iy <= -1.0f || iy >= (float)HI) continue;

        // group x-range reject over the 96-px span (ax > 0, monotone)
        const float ix0 = fmaf(p.x, fpx0, p.y);
        const float ix3 = fmaf(p.x, 96.0f, ix0);
        if (ix3 <= -1.0f || ix0 >= (float)WI) continue;

        // y setup once per layer (shared by all 4 px)
        const float y0f = floorf(iy);
        const float wy1 = iy - y0f;
        const float wy0 = 1.0f - wy1;
        const int   y0  = (int)y0f;
        const int   y1  = y0 + 1;
        const bool  y_int = (iy >= 0.0f) && (iy < (float)(HI - 1));
        const float wyv0 = (y0 >= 0 && y0 < HI) ? wy0 : 0.0f;
        const float wyv1 = (y1 >= 0 && y1 < HI) ? wy1 : 0.0f;
        const int y0c = min(max(y0, 0), HI - 1);
        const int y1c = min(max(y1, 0), HI - 1);
        const float my = wyv0 + wyv1;

        const float* sbase = src + (size_t)n * CCH * HI * WI;
        const float* ri0 = sbase + y0c * WI;   // clamped rows (==y0 when y_int)
        const float* ri1 = sbase + y1c * WI;

#pragma unroll
        for (int j = 0; j < 4; j++) {
            const float ix = fmaf(p.x, (float)(j * 32), ix0);
            if (ix <= -1.0f || ix >= (float)WI) continue;   // this px outside

            const float x0f = floorf(ix);
            const float wx1 = ix - x0f;
            const float wx0 = 1.0f - wx1;
            const int   x0  = (int)x0f;

            const bool intr = y_int && (ix >= 0.0f) && (ix < (float)(WI - 1));

            if (intr) {
                // m == 1: overwrites everything below this px.
                const float w00 = wy0 * wx0, w10 = wy1 * wx0;
                const float w01 = wy0 * wx1, w11 = wy1 * wx1;
#pragma unroll
                for (int c = 0; c < CCH; c++) {
                    const float* rc0 = ri0 + c * (HI * WI);
                    const float* rc1 = ri1 + c * (HI * WI);
                    const float v00 = __ldg(rc0 + x0);
                    const float v10 = __ldg(rc1 + x0);
                    const float v01 = __ldg(rc0 + x0 + 1);
                    const float v11 = __ldg(rc1 + x0 + 1);
                    const float s = fmaf(v11, w11, fmaf(v10, w10,
                                    fmaf(v01, w01, v00 * w00)));
                    A[c][j] = fmaf(T[j], s, A[c][j]);
                }
                T[j] = 0.0f;
            } else {
                // Boundary path: full reference semantics.
                const int   x1  = x0 + 1;
                const float wxv0 = (x0 >= 0 && x0 < WI) ? wx0 : 0.0f;
                const float wxv1 = (x1 >= 0 && x1 < WI) ? wx1 : 0.0f;
                const int x0c = min(max(x0, 0), WI - 1);
                const int x1c = min(max(x1, 0), WI - 1);

                const float m = my * (wxv0 + wxv1);
                if (m == 0.0f) continue;
                const float wgt = T[j] * m;
#pragma unroll
                for (int c = 0; c < CCH; c++) {
                    const float* rc0 = ri0 + c * (HI * WI);
                    const float* rc1 = ri1 + c * (HI * WI);
                    const float v00 = __ldg(rc0 + x0c);
                    const float v10 = __ldg(rc1 + x0c);
                    const float v01 = __ldg(rc0 + x1c);
                    const float v11 = __ldg(rc1 + x1c);
                    const float rowA = v00 * wyv0 + v10 * wyv1;
                    const float rowB = v01 * wyv0 + v11 * wyv1;
                    const float s = rowA * wxv0 + rowB * wxv1;
                    A[c][j] = fmaf(wgt, s, A[c][j]);
                }
                T[j] *= (1.0f - m);
            }
        }

        // All 4 px fully opaque -> earlier layers and bg are invisible.
        const float Tm = fmaxf(fmaxf(T[0], T[1]), fmaxf(T[2], T[3]));
        if (Tm == 0.0f) break;
    }

    // Background contribution only where transparency survives.
    const float Tmax = fmaxf(fmaxf(T[0], T[1]), fmaxf(T[2], T[3]));
    if (Tmax > 0.0f) {
#pragma unroll
        for (int j = 0; j < 4; j++) {
            if (T[j] > 0.0f) {
#pragma unroll
                for (int c = 0; c < CCH; c++) {
                    const float bv = __ldcs(bg + c * HW + base + j * 32);
                    A[c][j] = fmaf(bv, T[j], A[c][j]);
                }
            }
        }
    }

    // Streaming scalar stores: lane-contiguous -> 128B per instruction.
#pragma unroll
    for (int c = 0; c < CCH; c++) {
#pragma unroll
        for (int j = 0; j < 4; j++) {
            __stcs(out + c * HW + base + j * 32, A[c][j]);
        }
    }
}

extern "C" void kernel_launch(void* const* d_in, const int* in_sizes, int n_in,
                              void* d_out, int out_size) {
    const float* src  = (const float*)d_in[0];  // [8,3,512,512]
    const float* bg   = (const float*)d_in[1];  // [1,3,2048,2048]
    const float* coor = (const float*)d_in[2];  // [8,4]
    float* out = (float*)d_out;                 // [1,3,2048,2048]

    dim3 block(32, 4);                    // 128 threads
    dim3 grid(WO / 128, HO / 4);          // (16, 512) = 8192 blocks
    composite_kernel<<<grid, block>>>(src, bg, coor, out);
}